// round 17
// baseline (speedup 1.0000x reference)
#include <cuda_runtime.h>
#include <cstdint>

#define Himg 512
#define Wimg 512
#define HW   (Himg * Wimg)          // 262144 = 2^18
#define HW4  (HW / 4)               // 65536 = 2^16
#define Bb   8
#define Cc   19
#define NPIX (Bb * HW)              // 2097152
#define NQ   (NPIX / 4)             // 524288 pixel-quads
#define NTHR 128
#define OCC  4
#define NBLK 512                     // NQ / (NBLK*NTHR) = 8 iters exactly
#define NACC 41

// Scratch (no allocations allowed -> __device__ globals)
__device__ unsigned char g_diff4[4][(Himg - 2) * Wimg];
__device__ float         g_wmap[HW];
__device__ double        g_coltot[NACC];
__device__ int           g_hist[Cc];
__device__ unsigned int  g_count;

// ---------------------------------------------------------------------------
// Boundary phase 1, split x4 over batch pairs (R13 proven). Zeroes g_hist.
// ---------------------------------------------------------------------------
__global__ void diff_kernel(const int* __restrict__ tgt) {
    int idx = blockIdx.x * blockDim.x + threadIdx.x;
    if (blockIdx.x == 0 && threadIdx.x < Cc) g_hist[threadIdx.x] = 0;
    const int N1 = (Himg - 2) * (Wimg / 4);
    if (idx >= 4 * N1) return;
    int q   = idx / N1;
    int rem = idx - q * N1;
    int i   = rem / (Wimg / 4);
    int w4  = rem - i * (Wimg / 4);
    int d0 = 0, d1 = 0, d2 = 0, d3 = 0;
#pragma unroll
    for (int bb = 0; bb < 2; bb++) {
        const int4* tp = (const int4*)(tgt + (2 * q + bb) * HW + i * Wimg) + w4;
        int4 a = tp[0];
        int4 e = tp[Wimg / 4];
        int4 c = tp[2 * (Wimg / 4)];
        d0 |= (a.x != e.x) | (e.x != c.x);
        d1 |= (a.y != e.y) | (e.y != c.y);
        d2 |= (a.z != e.z) | (e.z != c.z);
        d3 |= (a.w != e.w) | (e.w != c.w);
    }
    uchar4 r;
    r.x = (unsigned char)d0; r.y = (unsigned char)d1;
    r.z = (unsigned char)d2; r.w = (unsigned char)d3;
    ((uchar4*)g_diff4[q])[rem] = r;
}

// ---------------------------------------------------------------------------
// Boundary phase 2 + target histogram; resets g_coltot and the ticket.
// ---------------------------------------------------------------------------
__global__ void wmap_kernel(const int* __restrict__ tgt) {
    __shared__ int h[Cc];
    if (threadIdx.x < Cc) h[threadIdx.x] = 0;
    __syncthreads();

    int idx = blockIdx.x * blockDim.x + threadIdx.x;
    if (idx == 0) g_count = 0;
    if (idx < NACC) g_coltot[idx] = 0.0;
    if (idx < HW) {
        int hh = idx >> 9;
        int w  = idx & (Wimg - 1);
        float v = 1.0f;
        if (hh >= 1 && hh <= Himg - 2 && w >= 1 && w <= Wimg - 2) {
            int i = hh - 1, j = w - 1;
            int d = 0;
#pragma unroll
            for (int q = 0; q < 4; q++)
                d |= g_diff4[q][i * Wimg + j] | g_diff4[q][i * Wimg + j + 1]
                   | g_diff4[q][i * Wimg + j + 2];
            if (d) v = 1.5f;
        }
        g_wmap[idx] = v;
#pragma unroll
        for (int b = 0; b < Bb; b++) atomicAdd(&h[tgt[b * HW + idx]], 1);
    }
    __syncthreads();
    if (threadIdx.x < Cc) atomicAdd(&g_hist[threadIdx.x], h[threadIdx.x]);
}

// ---------------------------------------------------------------------------
// Main streaming reduction, float4-vectorized, instruction-lean (R13 body;
// __ldg keeps lines L1-resident for the x[target] gather).
// Fused ticketed micro-epilogue via double atomics.
// ---------------------------------------------------------------------------
__global__ void __launch_bounds__(NTHR, OCC)
main_kernel(const float* __restrict__ in, const int* __restrict__ tgt,
            float* __restrict__ out) {
    __shared__ float sm_inter[Cc];
    if (threadIdx.x < Cc) sm_inter[threadIdx.x] = 0.0f;
    __syncthreads();

    float denom[Cc];
#pragma unroll
    for (int c = 0; c < Cc; c++) denom[c] = 0.0f;
    float facc = 0.0f, ceacc = 0.0f, bacc = 0.0f;

    const int stride = gridDim.x * blockDim.x;        // 65536
    for (int p = blockIdx.x * blockDim.x + threadIdx.x; p < NQ; p += stride) {
        int hw4 = p & (HW4 - 1);
        int b   = p >> 16;
        const float* base = in + (size_t)(b * Cc) * HW + 4 * (size_t)hw4;

        float4 x[Cc];
#pragma unroll
        for (int c = 0; c < Cc; c++)
            x[c] = __ldg((const float4*)(base + (size_t)c * HW));

        int4   t4 = ((const int4*)tgt)[p];
        float4 w4 = ((const float4*)g_wmap)[hw4];

        // gather x[target] (lines L1-resident from the loads above)
        float xt0 = __ldg(base + (size_t)t4.x * HW + 0);
        float xt1 = __ldg(base + (size_t)t4.y * HW + 1);
        float xt2 = __ldg(base + (size_t)t4.z * HW + 2);
        float xt3 = __ldg(base + (size_t)t4.w * HW + 3);

        float s0 = 0.0f, s1 = 0.0f, s2 = 0.0f, s3 = 0.0f;
        float u0 = 0.0f, u1 = 0.0f, u2 = 0.0f, u3 = 0.0f;
#pragma unroll
        for (int c = 0; c < Cc; c++) {
            u0 += x[c].x; u1 += x[c].y; u2 += x[c].z; u3 += x[c].w;
            float e0 = __expf(x[c].x);
            float e1 = __expf(x[c].y);
            float e2 = __expf(x[c].z);
            float e3 = __expf(x[c].w);
            s0 += e0; s1 += e1; s2 += e2; s3 += e3;
            x[c].x = e0; x[c].y = e1; x[c].z = e2; x[c].w = e3;
        }
        float i0 = __fdividef(1.0f, s0);
        float i1 = __fdividef(1.0f, s1);
        float i2 = __fdividef(1.0f, s2);
        float i3 = __fdividef(1.0f, s3);
        float z0 = __logf(s0), z1 = __logf(s1), z2 = __logf(s2), z3 = __logf(s3);
        float n0 = z0 - xt0, n1 = z1 - xt1, n2 = z2 - xt2, n3 = z3 - xt3;
        float p0 = __expf(xt0) * i0;
        float p1 = __expf(xt1) * i1;
        float p2 = __expf(xt2) * i2;
        float p3 = __expf(xt3) * i3;

#pragma unroll
        for (int c = 0; c < Cc; c++)
            denom[c] = fmaf(x[c].x, i0, fmaf(x[c].y, i1,
                       fmaf(x[c].z, i2, fmaf(x[c].w, i3, denom[c]))));

        atomicAdd(&sm_inter[t4.x], p0);
        atomicAdd(&sm_inter[t4.y], p1);
        atomicAdd(&sm_inter[t4.z], p2);
        atomicAdd(&sm_inter[t4.w], p3);

        float o0 = 1.0f - p0, o1 = 1.0f - p1, o2 = 1.0f - p2, o3 = 1.0f - p3;
        facc  = fmaf(o0 * o0, n0, fmaf(o1 * o1, n1,
                fmaf(o2 * o2, n2, fmaf(o3 * o3, n3, facc))));
        ceacc += 0.9f * (n0 + n1 + n2 + n3)
               + 0.1f * ((z0 + z1 + z2 + z3) - (u0 + u1 + u2 + u3) * (1.0f / Cc));
        bacc  = fmaf(n0, w4.x, fmaf(n1, w4.y, fmaf(n2, w4.z, fmaf(n3, w4.w, bacc))));
    }

    // ---- block reduction: warp shuffles -> fixed-order smem ----
    __shared__ float sm[NTHR / 32][22];
    int wid  = threadIdx.x >> 5;
    int lane = threadIdx.x & 31;

#pragma unroll
    for (int c = 0; c < Cc; c++) {
        float v = denom[c];
#pragma unroll
        for (int o = 16; o > 0; o >>= 1) v += __shfl_xor_sync(0xffffffffu, v, o);
        denom[c] = v;
    }
#pragma unroll
    for (int o = 16; o > 0; o >>= 1) facc  += __shfl_xor_sync(0xffffffffu, facc, o);
#pragma unroll
    for (int o = 16; o > 0; o >>= 1) ceacc += __shfl_xor_sync(0xffffffffu, ceacc, o);
#pragma unroll
    for (int o = 16; o > 0; o >>= 1) bacc  += __shfl_xor_sync(0xffffffffu, bacc, o);

    if (lane == 0) {
#pragma unroll
        for (int c = 0; c < Cc; c++) sm[wid][c] = denom[c];
        sm[wid][19] = facc;
        sm[wid][20] = ceacc;
        sm[wid][21] = bacc;
    }
    __syncthreads();

    if (threadIdx.x < Cc) {                       // denom columns
        float s = 0.0f;
#pragma unroll
        for (int w = 0; w < NTHR / 32; w++) s += sm[w][threadIdx.x];
        atomicAdd(&g_coltot[threadIdx.x], (double)s);
    } else if (threadIdx.x < 2 * Cc) {            // inter columns (from smem)
        atomicAdd(&g_coltot[threadIdx.x], (double)sm_inter[threadIdx.x - Cc]);
    } else if (threadIdx.x < NACC) {              // focal / ce / boundary
        int k = threadIdx.x - 2 * Cc;             // 0,1,2
        float s = 0.0f;
#pragma unroll
        for (int w = 0; w < NTHR / 32; w++) s += sm[w][19 + k];
        atomicAdd(&g_coltot[threadIdx.x], (double)s);
    }

    // ---- last-block-done ticket -> micro-epilogue ----
    __shared__ bool is_last;
    __threadfence();
    __syncthreads();
    if (threadIdx.x == 0) {
        unsigned int r = atomicAdd(&g_count, 1u);
        is_last = (r == (unsigned int)(gridDim.x - 1));
    }
    __syncthreads();
    if (!is_last) return;
    __threadfence();

    __shared__ double tot[NACC];
    if (threadIdx.x < NACC) tot[threadIdx.x] = __ldcg(&g_coltot[threadIdx.x]);
    __syncthreads();
    if (threadIdx.x == 0) {
        const double inv = 1.0 / (double)NPIX;
        double focal = tot[38] * inv;
        double ce    = tot[39] * inv;
        double bnd   = tot[40] * inv;
        double dice  = 0.0;
        for (int c = 0; c < Cc; c++) {
            double den = tot[c] + (double)g_hist[c];
            dice += 1.0 - (2.0 * tot[19 + c] + 1e-5) / (den + 1e-5);
        }
        dice /= (double)Cc;
        out[0] = (float)focal;
        out[1] = (float)dice;
        out[2] = (float)ce;
        out[3] = (float)bnd;
        out[4] = (float)(focal + dice + ce + bnd);
    }
}

extern "C" void kernel_launch(void* const* d_in, const int* in_sizes, int n_in,
                              void* d_out, int out_size) {
    const float* in  = (const float*)d_in[0];  // [8,19,512,512] f32
    const int*   tgt = (const int*)d_in[1];    // [8,512,512] i32
    float*       out = (float*)d_out;          // [5] f32

    diff_kernel<<<(4 * (Himg - 2) * (Wimg / 4) + 255) / 256, 256>>>(tgt);
    wmap_kernel<<<HW / 256, 256>>>(tgt);
    main_kernel<<<NBLK, NTHR>>>(in, tgt, out);
}